// round 12
// baseline (speedup 1.0000x reference)
#include <cuda_runtime.h>
#include <cuda_bf16.h>
#include <math.h>

#define B_SZ 256
#define D_SZ 512

// ---------------- scratch (device globals; no allocation allowed) ----------
__device__ float g_q[B_SZ * D_SZ];
__device__ float g_k[B_SZ * D_SZ];
__device__ float g_v[B_SZ * D_SZ];
__device__ float g_o[B_SZ * D_SZ];
__device__ float g_it[B_SZ];
__device__ float g_ft[B_SZ];
__device__ float g_ht[B_SZ * D_SZ];

// ---------------- projection GEMM + gates -----------------------------------
// z<4:  Y[256,512] = X[256,512] @ W[512,512]^T -- L2-DIRECT version.
//       64x64 tile, 256 threads, 4x4 outputs/thread, NO shared memory,
//       NO barriers. Operands are L2-resident (W=1MB, X=0.5MB); A-row loads
//       broadcast-coalesce across 16 lanes; redundancy is absorbed by L2 BW.
// z==4: gate kernel (one warp per batch row).
#define BM 64
#define BN 64

__global__ __launch_bounds__(256) void proj_gemm(
    const float* __restrict__ X,
    const float* __restrict__ Wq, const float* __restrict__ Wk,
    const float* __restrict__ Wv, const float* __restrict__ Wo,
    const float* __restrict__ Wo_b,
    const float* __restrict__ wi_w, const float* __restrict__ wi_b,
    const float* __restrict__ wf_w, const float* __restrict__ wf_b)
{
    // ---- z==4: gates (32 blocks x 8 warps = 256 warps = 1/batch row) ----
    if (blockIdx.z == 4) {
        const int warp = threadIdx.x >> 5;
        const int lane = threadIdx.x & 31;
        const int b    = (blockIdx.y * 8 + blockIdx.x) * 8 + warp;

        const float4* x4  = (const float4*)(X + (size_t)b * D_SZ);
        const float4* wi4 = (const float4*)wi_w;
        const float4* wf4 = (const float4*)wf_w;

        float si = 0.f, sf = 0.f;
        #pragma unroll
        for (int r = 0; r < 4; ++r) {
            float4 x  = x4[lane + r * 32];
            float4 wi = wi4[lane + r * 32];
            float4 wf = wf4[lane + r * 32];
            si += x.x * wi.x + x.y * wi.y + x.z * wi.z + x.w * wi.w;
            sf += x.x * wf.x + x.y * wf.y + x.z * wf.z + x.w * wf.w;
        }
        #pragma unroll
        for (int o = 16; o; o >>= 1) {
            si += __shfl_down_sync(0xffffffffu, si, o);
            sf += __shfl_down_sync(0xffffffffu, sf, o);
        }
        if (lane == 0) {
            g_it[b] = fminf(expf(si + wi_b[0]), 50.0f);
            g_ft[b] = 1.0f / (1.0f + expf(-(sf + wf_b[0])));
        }
        return;
    }

    // ---- z<4: L2-direct GEMM ----
    const float* W;
    float* Y;
    bool act = false;
    switch (blockIdx.z) {
        case 0: W = Wq; Y = g_q; break;
        case 1: W = Wk; Y = g_k; break;
        case 2: W = Wv; Y = g_v; break;
        default: W = Wo; Y = g_o; act = true; break;
    }

    const int tid = threadIdx.x;
    const int m0  = blockIdx.y * BM;
    const int n0  = blockIdx.x * BN;
    const int ty  = tid >> 4;          // 0..15 -> 4 M-rows
    const int tx  = tid & 15;          // 0..15 -> 4 N-cols

    const float* A0 = X + (size_t)(m0 + ty * 4 + 0) * D_SZ;
    const float* A1 = X + (size_t)(m0 + ty * 4 + 1) * D_SZ;
    const float* A2 = X + (size_t)(m0 + ty * 4 + 2) * D_SZ;
    const float* A3 = X + (size_t)(m0 + ty * 4 + 3) * D_SZ;
    const float* B0 = W + (size_t)(n0 + tx * 4 + 0) * D_SZ;
    const float* B1 = W + (size_t)(n0 + tx * 4 + 1) * D_SZ;
    const float* B2 = W + (size_t)(n0 + tx * 4 + 2) * D_SZ;
    const float* B3 = W + (size_t)(n0 + tx * 4 + 3) * D_SZ;

    float acc[4][4] = {};

    #pragma unroll 8
    for (int k0 = 0; k0 < D_SZ; k0 += 4) {
        const float4 a0 = *(const float4*)(A0 + k0);
        const float4 a1 = *(const float4*)(A1 + k0);
        const float4 a2 = *(const float4*)(A2 + k0);
        const float4 a3 = *(const float4*)(A3 + k0);
        const float4 b0 = *(const float4*)(B0 + k0);
        const float4 b1 = *(const float4*)(B1 + k0);
        const float4 b2 = *(const float4*)(B2 + k0);
        const float4 b3 = *(const float4*)(B3 + k0);

        acc[0][0] += a0.x*b0.x + a0.y*b0.y + a0.z*b0.z + a0.w*b0.w;
        acc[0][1] += a0.x*b1.x + a0.y*b1.y + a0.z*b1.z + a0.w*b1.w;
        acc[0][2] += a0.x*b2.x + a0.y*b2.y + a0.z*b2.z + a0.w*b2.w;
        acc[0][3] += a0.x*b3.x + a0.y*b3.y + a0.z*b3.z + a0.w*b3.w;
        acc[1][0] += a1.x*b0.x + a1.y*b0.y + a1.z*b0.z + a1.w*b0.w;
        acc[1][1] += a1.x*b1.x + a1.y*b1.y + a1.z*b1.z + a1.w*b1.w;
        acc[1][2] += a1.x*b2.x + a1.y*b2.y + a1.z*b2.z + a1.w*b2.w;
        acc[1][3] += a1.x*b3.x + a1.y*b3.y + a1.z*b3.z + a1.w*b3.w;
        acc[2][0] += a2.x*b0.x + a2.y*b0.y + a2.z*b0.z + a2.w*b0.w;
        acc[2][1] += a2.x*b1.x + a2.y*b1.y + a2.z*b1.z + a2.w*b1.w;
        acc[2][2] += a2.x*b2.x + a2.y*b2.y + a2.z*b2.z + a2.w*b2.w;
        acc[2][3] += a2.x*b3.x + a2.y*b3.y + a2.z*b3.z + a2.w*b3.w;
        acc[3][0] += a3.x*b0.x + a3.y*b0.y + a3.z*b0.z + a3.w*b0.w;
        acc[3][1] += a3.x*b1.x + a3.y*b1.y + a3.z*b1.z + a3.w*b1.w;
        acc[3][2] += a3.x*b2.x + a3.y*b2.y + a3.z*b2.z + a3.w*b2.w;
        acc[3][3] += a3.x*b3.x + a3.y*b3.y + a3.z*b3.z + a3.w*b3.w;
    }

    const int row = m0 + ty * 4;
    const int col = n0 + tx * 4;
    #pragma unroll
    for (int i = 0; i < 4; ++i) {
        float4 r;
        r.x = acc[i][0]; r.y = acc[i][1]; r.z = acc[i][2]; r.w = acc[i][3];
        if (act) {
            r.x = 1.0f / (1.0f + __expf(-(r.x + Wo_b[col + 0])));
            r.y = 1.0f / (1.0f + __expf(-(r.y + Wo_b[col + 1])));
            r.z = 1.0f / (1.0f + __expf(-(r.z + Wo_b[col + 2])));
            r.w = 1.0f / (1.0f + __expf(-(r.w + Wo_b[col + 3])));
        }
        *(float4*)(Y + (size_t)(row + i) * D_SZ + col) = r;
    }
}

// ---------------- fused cell kernel: C_t + h_tilde partial ------------------
// grid(32, 256): 16 rows per block, 16 threads per row, float4 streaming.
__global__ __launch_bounds__(256) void cell_kernel(
    const float* __restrict__ Cprev, float* __restrict__ Ct)
{
    __shared__ __align__(16) float sk[D_SZ];
    __shared__ __align__(16) float sq[D_SZ];
    __shared__ float sv[16];

    const int b   = blockIdx.y;
    const int rb  = blockIdx.x;       // row block 0..31
    const int tid = threadIdx.x;      // 0..255

    if (tid < 128) {
        ((float4*)sk)[tid] = ((const float4*)(g_k + (size_t)b * D_SZ))[tid];
    } else {
        ((float4*)sq)[tid - 128] = ((const float4*)(g_q + (size_t)b * D_SZ))[tid - 128];
    }
    if (tid < 16) sv[tid] = g_v[(size_t)b * D_SZ + rb * 16 + tid];
    __syncthreads();

    const float f  = g_ft[b];
    const float it = g_it[b];
    const int r      = tid >> 4;       // local row 0..15
    const int lane16 = tid & 15;
    const int row    = rb * 16 + r;
    const float ivi  = it * sv[r];

    const float4* cp = (const float4*)(Cprev + (size_t)b * D_SZ * D_SZ + (size_t)row * D_SZ);
    float4*       ct = (float4*)(Ct   + (size_t)b * D_SZ * D_SZ + (size_t)row * D_SZ);
    const float4* k4 = (const float4*)sk;
    const float4* q4 = (const float4*)sq;

    float ht = 0.f;
    #pragma unroll
    for (int j = 0; j < 8; ++j) {
        const int idx = lane16 + j * 16;
        float4 c  = __ldcs(cp + idx);          // stream: no reuse
        float4 kv = k4[idx];
        float4 qv = q4[idx];
        float4 o;
        o.x = f * c.x + ivi * kv.x;
        o.y = f * c.y + ivi * kv.y;
        o.z = f * c.z + ivi * kv.z;
        o.w = f * c.w + ivi * kv.w;
        __stcs(ct + idx, o);                   // stream: no reuse
        ht += o.x * qv.x + o.y * qv.y + o.z * qv.z + o.w * qv.w;
    }
    #pragma unroll
    for (int off = 8; off; off >>= 1)
        ht += __shfl_down_sync(0xffffffffu, ht, off, 16);
    if (lane16 == 0) g_ht[(size_t)b * D_SZ + row] = ht;
}

// ---------------- epilogue: n_t, nq, h, LayerNorm ---------------------------
// 256 blocks x 256 threads; ALL global loads issued before first reduction;
// mean+variance fused into one packed float2 reduction (2 barrier rounds total).
__global__ __launch_bounds__(256) void epilogue_kernel(
    const float* __restrict__ n_prev,
    const float* __restrict__ ln_g, const float* __restrict__ ln_b,
    float* __restrict__ out_h, float* __restrict__ out_n)
{
    __shared__ float  red1[8];
    __shared__ float2 red2[8];

    const int b   = blockIdx.x;
    const int tid = threadIdx.x;
    const int e0  = tid;
    const int e1  = tid + 256;
    const size_t base = (size_t)b * D_SZ;

    const float f  = g_ft[b];
    const float it = g_it[b];

    // ---- issue every global load up front (overlap latency with reductions)
    const float np0 = n_prev[base + e0], np1 = n_prev[base + e1];
    const float k0  = g_k[base + e0],   k1  = g_k[base + e1];
    const float q0  = g_q[base + e0],   q1  = g_q[base + e1];
    const float o0  = g_o[base + e0],   o1  = g_o[base + e1];
    const float t0  = g_ht[base + e0],  t1  = g_ht[base + e1];
    const float gg0 = ln_g[e0],         gg1 = ln_g[e1];
    const float bb0 = ln_b[e0],         bb1 = ln_b[e1];

    const float nt0 = f * np0 + it * k0;
    const float nt1 = f * np1 + it * k1;
    out_n[base + e0] = nt0;
    out_n[base + e1] = nt1;

    // ---- reduction 1: nq
    float nq = nt0 * q0 + nt1 * q1;
    {
        #pragma unroll
        for (int o = 16; o; o >>= 1) nq += __shfl_down_sync(0xffffffffu, nq, o);
        const int w = tid >> 5;
        if ((tid & 31) == 0) red1[w] = nq;
        __syncthreads();
        if (tid < 8) {
            float s = red1[tid];
            #pragma unroll
            for (int o = 4; o; o >>= 1) s += __shfl_down_sync(0xffu, s, o);
            if (tid == 0) red1[0] = s;
        }
        __syncthreads();
        nq = red1[0];
    }
    const float inv_den = 1.0f / fmaxf(fabsf(nq), 1.0f);

    const float h0 = o0 * t0 * inv_den;
    const float h1 = o1 * t1 * inv_den;

    // ---- reduction 2 (packed): sum(h), sum(h^2)
    float s  = h0 + h1;
    float s2 = h0 * h0 + h1 * h1;
    {
        #pragma unroll
        for (int o = 16; o; o >>= 1) {
            s  += __shfl_down_sync(0xffffffffu, s,  o);
            s2 += __shfl_down_sync(0xffffffffu, s2, o);
        }
        const int w = tid >> 5;
        if ((tid & 31) == 0) red2[w] = make_float2(s, s2);
        __syncthreads();
        if (tid < 8) {
            float2 v = red2[tid];
            #pragma unroll
            for (int o = 4; o; o >>= 1) {
                v.x += __shfl_down_sync(0xffu, v.x, o);
                v.y += __shfl_down_sync(0xffu, v.y, o);
            }
            if (tid == 0) red2[0] = v;
        }
        __syncthreads();
        s  = red2[0].x;
        s2 = red2[0].y;
    }

    const float mu   = s * (1.0f / (float)D_SZ);
    const float var  = fmaxf(s2 * (1.0f / (float)D_SZ) - mu * mu, 0.0f);
    const float rstd = rsqrtf(var + 1e-5f);

    out_h[base + e0] = (h0 - mu) * rstd * gg0 + bb0;
    out_h[base + e1] = (h1 - mu) * rstd * gg1 + bb1;
}

// ---------------- launch ----------------------------------------------------
extern "C" void kernel_launch(void* const* d_in, const int* in_sizes, int n_in,
                              void* d_out, int out_size)
{
    const float* x_t    = (const float*)d_in[0];
    const float* C_prev = (const float*)d_in[1];
    const float* n_prev = (const float*)d_in[2];
    const float* Wq     = (const float*)d_in[3];
    const float* Wk     = (const float*)d_in[4];
    const float* Wv     = (const float*)d_in[5];
    const float* wi_w   = (const float*)d_in[6];
    const float* wi_b   = (const float*)d_in[7];
    const float* wf_w   = (const float*)d_in[8];
    const float* wf_b   = (const float*)d_in[9];
    const float* Wo     = (const float*)d_in[10];
    const float* Wo_b   = (const float*)d_in[11];
    const float* ln_g   = (const float*)d_in[12];
    const float* ln_b   = (const float*)d_in[13];

    float* out   = (float*)d_out;
    float* out_h = out;                                       // [256,512]
    float* out_C = out + (size_t)B_SZ * D_SZ;                 // [256,512,512]
    float* out_n = out + (size_t)B_SZ * D_SZ + (size_t)B_SZ * D_SZ * D_SZ; // [256,512]

    dim3 ggrid(D_SZ / BN, B_SZ / BM, 5);                      // (8,4,5): 4 GEMMs + gates
    proj_gemm<<<ggrid, 256>>>(x_t, Wq, Wk, Wv, Wo, Wo_b,
                              wi_w, wi_b, wf_w, wf_b);
    cell_kernel<<<dim3(D_SZ / 16, B_SZ), 256>>>(C_prev, out_C);
    epilogue_kernel<<<B_SZ, 256>>>(n_prev, ln_g, ln_b, out_h, out_n);
}

// round 15
// speedup vs baseline: 1.7556x; 1.7556x over previous
#include <cuda_runtime.h>
#include <cuda_bf16.h>
#include <math.h>
#include <stdint.h>

#define B_SZ 256
#define D_SZ 512

// ---------------- scratch (device globals; no allocation allowed) ----------
__device__ float g_q[B_SZ * D_SZ];
__device__ float g_k[B_SZ * D_SZ];
__device__ float g_v[B_SZ * D_SZ];
__device__ float g_o[B_SZ * D_SZ];
__device__ float g_it[B_SZ];
__device__ float g_ft[B_SZ];
__device__ float g_ht[B_SZ * D_SZ];

// ---------------- tf32 helpers ---------------------------------------------
__device__ __forceinline__ uint32_t to_tf32(float x)
{
    uint32_t r;
    asm("cvt.rna.tf32.f32 %0, %1;" : "=r"(r) : "f"(x));
    return r;
}

__device__ __forceinline__ void mma_tf32(
    float& d0, float& d1, float& d2, float& d3,
    uint32_t a0, uint32_t a1, uint32_t a2, uint32_t a3,
    uint32_t b0, uint32_t b1)
{
    asm volatile(
        "mma.sync.aligned.m16n8k8.row.col.f32.tf32.tf32.f32 "
        "{%0,%1,%2,%3}, {%4,%5,%6,%7}, {%8,%9}, {%0,%1,%2,%3};"
        : "+f"(d0), "+f"(d1), "+f"(d2), "+f"(d3)
        : "r"(a0), "r"(a1), "r"(a2), "r"(a3), "r"(b0), "r"(b1));
}

// ---------------- projection GEMM (tensor cores) + gates --------------------
// z<4:  Y[256,512] = X[256,512] @ W[512,512]^T via m16n8k8 tf32 MMA with
//       3xTF32 hi/lo compensation (hi*hi + hi*lo + lo*hi) => ~fp32 accuracy.
//       64x64 tile, BK=32, 8 warps (4m x 2n), warp tile 16x32.
// z==4: gate kernel (one warp per batch row).
#define BKT 32
#define SPAD 65

__global__ __launch_bounds__(256) void proj_gemm(
    const float* __restrict__ X,
    const float* __restrict__ Wq, const float* __restrict__ Wk,
    const float* __restrict__ Wv, const float* __restrict__ Wo,
    const float* __restrict__ Wo_b,
    const float* __restrict__ wi_w, const float* __restrict__ wi_b,
    const float* __restrict__ wf_w, const float* __restrict__ wf_b)
{
    // ---- z==4: gates (32 blocks x 8 warps = 256 warps = 1/batch row) ----
    if (blockIdx.z == 4) {
        const int warp = threadIdx.x >> 5;
        const int lane = threadIdx.x & 31;
        const int b    = (blockIdx.y * 8 + blockIdx.x) * 8 + warp;

        const float4* x4  = (const float4*)(X + (size_t)b * D_SZ);
        const float4* wi4 = (const float4*)wi_w;
        const float4* wf4 = (const float4*)wf_w;

        float si = 0.f, sf = 0.f;
        #pragma unroll
        for (int r = 0; r < 4; ++r) {
            float4 x  = x4[lane + r * 32];
            float4 wi = wi4[lane + r * 32];
            float4 wf = wf4[lane + r * 32];
            si += x.x * wi.x + x.y * wi.y + x.z * wi.z + x.w * wi.w;
            sf += x.x * wf.x + x.y * wf.y + x.z * wf.z + x.w * wf.w;
        }
        #pragma unroll
        for (int o = 16; o; o >>= 1) {
            si += __shfl_down_sync(0xffffffffu, si, o);
            sf += __shfl_down_sync(0xffffffffu, sf, o);
        }
        if (lane == 0) {
            g_it[b] = fminf(expf(si + wi_b[0]), 50.0f);
            g_ft[b] = 1.0f / (1.0f + expf(-(sf + wf_b[0])));
        }
        return;
    }

    // ---- z<4: tf32 MMA GEMM ----
    const float* W;
    float* Y;
    bool act = false;
    switch (blockIdx.z) {
        case 0: W = Wq; Y = g_q; break;
        case 1: W = Wk; Y = g_k; break;
        case 2: W = Wv; Y = g_v; break;
        default: W = Wo; Y = g_o; act = true; break;
    }

    // smem: [k][m or n] layout, padded rows; values already tf32-rounded.
    __shared__ float Ah[BKT][SPAD], Al[BKT][SPAD];
    __shared__ float Bh[BKT][SPAD], Bl[BKT][SPAD];

    const int tid  = threadIdx.x;
    const int m0   = blockIdx.y * 64;
    const int n0   = blockIdx.x * 64;

    // staging: thread -> row (0..63), k-octet (0,8,16,24); 2 float4 per array.
    const int srow = tid >> 2;
    const int skq  = (tid & 3) * 8;
    const float* Ag = X + (size_t)(m0 + srow) * D_SZ + skq;
    const float* Bg = W + (size_t)(n0 + srow) * D_SZ + skq;

    const int lane = tid & 31;
    const int wid  = tid >> 5;
    const int wm   = wid >> 1;          // 0..3 -> m offset wm*16
    const int wn   = wid & 1;           // 0..1 -> n offset wn*32
    const int g    = lane >> 2;         // 0..7
    const int t    = lane & 3;          // 0..3

    float acc[4][4] = {};               // [ntile][d0..d3]

    float4 pa0 = *(const float4*)Ag;
    float4 pa1 = *(const float4*)(Ag + 4);
    float4 pb0 = *(const float4*)Bg;
    float4 pb1 = *(const float4*)(Bg + 4);

    const int NT = D_SZ / BKT;          // 16 tiles
    for (int tile = 0; tile < NT; ++tile) {
        // ---- store staged tile with hi/lo tf32 split (transposed to [k][*])
        {
            const float va[8] = {pa0.x, pa0.y, pa0.z, pa0.w, pa1.x, pa1.y, pa1.z, pa1.w};
            const float vb[8] = {pb0.x, pb0.y, pb0.z, pb0.w, pb1.x, pb1.y, pb1.z, pb1.w};
            #pragma unroll
            for (int j = 0; j < 8; ++j) {
                const int k = skq + j;
                float ah = __uint_as_float(to_tf32(va[j]));
                Ah[k][srow] = ah;
                Al[k][srow] = __uint_as_float(to_tf32(va[j] - ah));
                float bh = __uint_as_float(to_tf32(vb[j]));
                Bh[k][srow] = bh;
                Bl[k][srow] = __uint_as_float(to_tf32(vb[j] - bh));
            }
        }
        __syncthreads();

        // ---- prefetch next tile's globals (latency overlaps MMA phase)
        if (tile + 1 < NT) {
            const int off = (tile + 1) * BKT;
            pa0 = *(const float4*)(Ag + off);
            pa1 = *(const float4*)(Ag + off + 4);
            pb0 = *(const float4*)(Bg + off);
            pb1 = *(const float4*)(Bg + off + 4);
        }

        // ---- 4 k8-steps of MMA
        #pragma unroll
        for (int ks = 0; ks < 4; ++ks) {
            const int k0 = ks * 8;
            const int ma = wm * 16 + g;
            const uint32_t ah0 = __float_as_uint(Ah[k0 + t    ][ma]);
            const uint32_t ah1 = __float_as_uint(Ah[k0 + t    ][ma + 8]);
            const uint32_t ah2 = __float_as_uint(Ah[k0 + t + 4][ma]);
            const uint32_t ah3 = __float_as_uint(Ah[k0 + t + 4][ma + 8]);
            const uint32_t al0 = __float_as_uint(Al[k0 + t    ][ma]);
            const uint32_t al1 = __float_as_uint(Al[k0 + t    ][ma + 8]);
            const uint32_t al2 = __float_as_uint(Al[k0 + t + 4][ma]);
            const uint32_t al3 = __float_as_uint(Al[k0 + t + 4][ma + 8]);

            #pragma unroll
            for (int j = 0; j < 4; ++j) {
                const int nb = wn * 32 + j * 8 + g;
                const uint32_t bh0 = __float_as_uint(Bh[k0 + t    ][nb]);
                const uint32_t bh1 = __float_as_uint(Bh[k0 + t + 4][nb]);
                const uint32_t bl0 = __float_as_uint(Bl[k0 + t    ][nb]);
                const uint32_t bl1 = __float_as_uint(Bl[k0 + t + 4][nb]);

                mma_tf32(acc[j][0], acc[j][1], acc[j][2], acc[j][3],
                         ah0, ah1, ah2, ah3, bh0, bh1);
                mma_tf32(acc[j][0], acc[j][1], acc[j][2], acc[j][3],
                         ah0, ah1, ah2, ah3, bl0, bl1);
                mma_tf32(acc[j][0], acc[j][1], acc[j][2], acc[j][3],
                         al0, al1, al2, al3, bh0, bh1);
            }
        }
        __syncthreads();
    }

    // ---- write outputs: d0/d1 -> (row g, cols 2t,2t+1); d2/d3 -> row g+8
    const int row0 = m0 + wm * 16 + g;
    const int row1 = row0 + 8;
    #pragma unroll
    for (int j = 0; j < 4; ++j) {
        const int colb = n0 + wn * 32 + j * 8 + 2 * t;
        float2 v0 = make_float2(acc[j][0], acc[j][1]);
        float2 v1 = make_float2(acc[j][2], acc[j][3]);
        if (act) {
            const float b0 = Wo_b[colb], b1 = Wo_b[colb + 1];
            v0.x = 1.0f / (1.0f + __expf(-(v0.x + b0)));
            v0.y = 1.0f / (1.0f + __expf(-(v0.y + b1)));
            v1.x = 1.0f / (1.0f + __expf(-(v1.x + b0)));
            v1.y = 1.0f / (1.0f + __expf(-(v1.y + b1)));
        }
        *(float2*)(Y + (size_t)row0 * D_SZ + colb) = v0;
        *(float2*)(Y + (size_t)row1 * D_SZ + colb) = v1;
    }
}

// ---------------- fused cell kernel: C_t + h_tilde partial ------------------
// grid(32, 256): 16 rows per block, 16 threads per row, float4 streaming.
__global__ __launch_bounds__(256) void cell_kernel(
    const float* __restrict__ Cprev, float* __restrict__ Ct)
{
    __shared__ __align__(16) float sk[D_SZ];
    __shared__ __align__(16) float sq[D_SZ];
    __shared__ float sv[16];

    const int b   = blockIdx.y;
    const int rb  = blockIdx.x;       // row block 0..31
    const int tid = threadIdx.x;      // 0..255

    if (tid < 128) {
        ((float4*)sk)[tid] = ((const float4*)(g_k + (size_t)b * D_SZ))[tid];
    } else {
        ((float4*)sq)[tid - 128] = ((const float4*)(g_q + (size_t)b * D_SZ))[tid - 128];
    }
    if (tid < 16) sv[tid] = g_v[(size_t)b * D_SZ + rb * 16 + tid];
    __syncthreads();

    const float f  = g_ft[b];
    const float it = g_it[b];
    const int r      = tid >> 4;       // local row 0..15
    const int lane16 = tid & 15;
    const int row    = rb * 16 + r;
    const float ivi  = it * sv[r];

    const float4* cp = (const float4*)(Cprev + (size_t)b * D_SZ * D_SZ + (size_t)row * D_SZ);
    float4*       ct = (float4*)(Ct   + (size_t)b * D_SZ * D_SZ + (size_t)row * D_SZ);
    const float4* k4 = (const float4*)sk;
    const float4* q4 = (const float4*)sq;

    float ht = 0.f;
    #pragma unroll
    for (int j = 0; j < 8; ++j) {
        const int idx = lane16 + j * 16;
        float4 c  = __ldcs(cp + idx);          // stream: no reuse
        float4 kv = k4[idx];
        float4 qv = q4[idx];
        float4 o;
        o.x = f * c.x + ivi * kv.x;
        o.y = f * c.y + ivi * kv.y;
        o.z = f * c.z + ivi * kv.z;
        o.w = f * c.w + ivi * kv.w;
        __stcs(ct + idx, o);                   // stream: no reuse
        ht += o.x * qv.x + o.y * qv.y + o.z * qv.z + o.w * qv.w;
    }
    #pragma unroll
    for (int off = 8; off; off >>= 1)
        ht += __shfl_down_sync(0xffffffffu, ht, off, 16);
    if (lane16 == 0) g_ht[(size_t)b * D_SZ + row] = ht;
}

// ---------------- epilogue: n_t, nq, h, LayerNorm ---------------------------
// 256 blocks x 256 threads; ALL global loads issued before first reduction;
// mean+variance fused into one packed float2 reduction (2 barrier rounds total).
__global__ __launch_bounds__(256) void epilogue_kernel(
    const float* __restrict__ n_prev,
    const float* __restrict__ ln_g, const float* __restrict__ ln_b,
    float* __restrict__ out_h, float* __restrict__ out_n)
{
    __shared__ float  red1[8];
    __shared__ float2 red2[8];

    const int b   = blockIdx.x;
    const int tid = threadIdx.x;
    const int e0  = tid;
    const int e1  = tid + 256;
    const size_t base = (size_t)b * D_SZ;

    const float f  = g_ft[b];
    const float it = g_it[b];

    // ---- issue every global load up front (overlap latency with reductions)
    const float np0 = n_prev[base + e0], np1 = n_prev[base + e1];
    const float k0  = g_k[base + e0],   k1  = g_k[base + e1];
    const float q0  = g_q[base + e0],   q1  = g_q[base + e1];
    const float o0  = g_o[base + e0],   o1  = g_o[base + e1];
    const float t0  = g_ht[base + e0],  t1  = g_ht[base + e1];
    const float gg0 = ln_g[e0],         gg1 = ln_g[e1];
    const float bb0 = ln_b[e0],         bb1 = ln_b[e1];

    const float nt0 = f * np0 + it * k0;
    const float nt1 = f * np1 + it * k1;
    out_n[base + e0] = nt0;
    out_n[base + e1] = nt1;

    // ---- reduction 1: nq
    float nq = nt0 * q0 + nt1 * q1;
    {
        #pragma unroll
        for (int o = 16; o; o >>= 1) nq += __shfl_down_sync(0xffffffffu, nq, o);
        const int w = tid >> 5;
        if ((tid & 31) == 0) red1[w] = nq;
        __syncthreads();
        if (tid < 8) {
            float s = red1[tid];
            #pragma unroll
            for (int o = 4; o; o >>= 1) s += __shfl_down_sync(0xffu, s, o);
            if (tid == 0) red1[0] = s;
        }
        __syncthreads();
        nq = red1[0];
    }
    const float inv_den = 1.0f / fmaxf(fabsf(nq), 1.0f);

    const float h0 = o0 * t0 * inv_den;
    const float h1 = o1 * t1 * inv_den;

    // ---- reduction 2 (packed): sum(h), sum(h^2)
    float s  = h0 + h1;
    float s2 = h0 * h0 + h1 * h1;
    {
        #pragma unroll
        for (int o = 16; o; o >>= 1) {
            s  += __shfl_down_sync(0xffffffffu, s,  o);
            s2 += __shfl_down_sync(0xffffffffu, s2, o);
        }
        const int w = tid >> 5;
        if ((tid & 31) == 0) red2[w] = make_float2(s, s2);
        __syncthreads();
        if (tid < 8) {
            float2 v = red2[tid];
            #pragma unroll
            for (int o = 4; o; o >>= 1) {
                v.x += __shfl_down_sync(0xffu, v.x, o);
                v.y += __shfl_down_sync(0xffu, v.y, o);
            }
            if (tid == 0) red2[0] = v;
        }
        __syncthreads();
        s  = red2[0].x;
        s2 = red2[0].y;
    }

    const float mu   = s * (1.0f / (float)D_SZ);
    const float var  = fmaxf(s2 * (1.0f / (float)D_SZ) - mu * mu, 0.0f);
    const float rstd = rsqrtf(var + 1e-5f);

    out_h[base + e0] = (h0 - mu) * rstd * gg0 + bb0;
    out_h[base + e1] = (h1 - mu) * rstd * gg1 + bb1;
}

// ---------------- launch ----------------------------------------------------
extern "C" void kernel_launch(void* const* d_in, const int* in_sizes, int n_in,
                              void* d_out, int out_size)
{
    const float* x_t    = (const float*)d_in[0];
    const float* C_prev = (const float*)d_in[1];
    const float* n_prev = (const float*)d_in[2];
    const float* Wq     = (const float*)d_in[3];
    const float* Wk     = (const float*)d_in[4];
    const float* Wv     = (const float*)d_in[5];
    const float* wi_w   = (const float*)d_in[6];
    const float* wi_b   = (const float*)d_in[7];
    const float* wf_w   = (const float*)d_in[8];
    const float* wf_b   = (const float*)d_in[9];
    const float* Wo     = (const float*)d_in[10];
    const float* Wo_b   = (const float*)d_in[11];
    const float* ln_g   = (const float*)d_in[12];
    const float* ln_b   = (const float*)d_in[13];

    float* out   = (float*)d_out;
    float* out_h = out;                                       // [256,512]
    float* out_C = out + (size_t)B_SZ * D_SZ;                 // [256,512,512]
    float* out_n = out + (size_t)B_SZ * D_SZ + (size_t)B_SZ * D_SZ * D_SZ; // [256,512]

    dim3 ggrid(8, 4, 5);                                      // 4 tf32 GEMMs + gates
    proj_gemm<<<ggrid, 256>>>(x_t, Wq, Wk, Wv, Wo, Wo_b,
                              wi_w, wi_b, wf_w, wf_b);
    cell_kernel<<<dim3(D_SZ / 16, B_SZ), 256>>>(C_prev, out_C);
    epilogue_kernel<<<B_SZ, 256>>>(n_prev, ln_g, ln_b, out_h, out_n);
}

// round 17
// speedup vs baseline: 1.8837x; 1.0730x over previous
#include <cuda_runtime.h>
#include <cuda_bf16.h>
#include <math.h>
#include <stdint.h>

#define B_SZ 256
#define D_SZ 512

// ---------------- scratch (device globals; no allocation allowed) ----------
__device__ float g_q[B_SZ * D_SZ];
__device__ float g_k[B_SZ * D_SZ];
__device__ float g_v[B_SZ * D_SZ];
__device__ float g_o[B_SZ * D_SZ];
__device__ float g_it[B_SZ];
__device__ float g_ft[B_SZ];
__device__ float g_ht[B_SZ * D_SZ];

// ---------------- tf32 helpers ---------------------------------------------
__device__ __forceinline__ uint32_t to_tf32(float x)
{
    uint32_t r;
    asm("cvt.rna.tf32.f32 %0, %1;" : "=r"(r) : "f"(x));
    return r;
}
__device__ __forceinline__ void split_tf32(float x, float& h, float& l)
{
    h = __uint_as_float(to_tf32(x));
    l = __uint_as_float(to_tf32(x - h));
}

__device__ __forceinline__ void mma_tf32(
    float& d0, float& d1, float& d2, float& d3,
    uint32_t a0, uint32_t a1, uint32_t a2, uint32_t a3,
    uint32_t b0, uint32_t b1)
{
    asm volatile(
        "mma.sync.aligned.m16n8k8.row.col.f32.tf32.tf32.f32 "
        "{%0,%1,%2,%3}, {%4,%5,%6,%7}, {%8,%9}, {%0,%1,%2,%3};"
        : "+f"(d0), "+f"(d1), "+f"(d2), "+f"(d3)
        : "r"(a0), "r"(a1), "r"(a2), "r"(a3), "r"(b0), "r"(b1));
}

// ---------------- projection GEMM (tensor cores, frag-major smem) ----------
// Y[256,512] = X[256,512] @ W[512,512]^T via m16n8k8 tf32 MMA, 3xTF32
// hi/lo compensation. 64x64 tile, BK=32, 8 warps (4m x 2n).
// Smem holds operands in MMA-FRAGMENT ORDER, split ONCE at staging:
//   AfH/AfL: frag (mt,ks,lane) -> 4 floats (16B)   [8 KB each]
//   BfH/BfL: frag (nsub,ks,lane) -> 2 floats (8B)  [8 KB each]
// All STS/LDS are wide and conflict-free.
__global__ __launch_bounds__(256) void proj_gemm(
    const float* __restrict__ X,
    const float* __restrict__ Wq, const float* __restrict__ Wk,
    const float* __restrict__ Wv, const float* __restrict__ Wo,
    const float* __restrict__ Wo_b)
{
    const float* W;
    float* Y;
    bool act = false;
    switch (blockIdx.z) {
        case 0: W = Wq; Y = g_q; break;
        case 1: W = Wk; Y = g_k; break;
        case 2: W = Wv; Y = g_v; break;
        default: W = Wo; Y = g_o; act = true; break;
    }

    __shared__ __align__(16) float AfH[2048], AfL[2048];
    __shared__ __align__(16) float BfH[2048], BfL[2048];

    const int tid  = threadIdx.x;
    const int m0   = blockIdx.y * 64;
    const int n0   = blockIdx.x * 64;
    const int lane = tid & 31;
    const int w    = tid >> 5;          // warp id, also staging block id
    const int g    = lane >> 2;         // 0..7
    const int t    = lane & 3;          // 0..3

    // ---- staging geometry (per thread, constant across tiles) ----
    // col within tile: shared by all this thread's frags
    const int ck   = (w & 3) * 8 + t;           // k offset in tile (0..31)
    // A frags: i=0 -> (mt = w>>2, ks = w&3); i=1 -> mt+2
    const int arow = m0 + (w >> 2) * 16 + g;
    // B frags: i=0..3 -> nsub = (w>>2) + 2*i, ks = w&3
    const int brow = n0 + (w >> 2) * 8 + g;

    // ---- MMA geometry ----
    const int wm = w >> 1;              // 0..3
    const int wn = w & 1;               // 0..1

    float acc[4][4] = {};

    // ---- preload tile 0 operands into registers ----
    float a[8], b[8];
    {
        const float* Xc = X + ck;
        const float* Wc = W + ck;
        a[0] = Xc[(size_t)(arow     ) * D_SZ];
        a[1] = Xc[(size_t)(arow +  8) * D_SZ];
        a[2] = Xc[(size_t)(arow     ) * D_SZ + 4];
        a[3] = Xc[(size_t)(arow +  8) * D_SZ + 4];
        a[4] = Xc[(size_t)(arow + 32) * D_SZ];
        a[5] = Xc[(size_t)(arow + 40) * D_SZ];
        a[6] = Xc[(size_t)(arow + 32) * D_SZ + 4];
        a[7] = Xc[(size_t)(arow + 40) * D_SZ + 4];
        #pragma unroll
        for (int i = 0; i < 4; ++i) {
            b[2 * i]     = Wc[(size_t)(brow + i * 16) * D_SZ];
            b[2 * i + 1] = Wc[(size_t)(brow + i * 16) * D_SZ + 4];
        }
    }

    const int NT = D_SZ / 32;           // 16 tiles
    for (int tile = 0; tile < NT; ++tile) {
        // ---- store staged frags (split once), wide conflict-free STS ----
        {
            float4 h4, l4;
            split_tf32(a[0], h4.x, l4.x); split_tf32(a[1], h4.y, l4.y);
            split_tf32(a[2], h4.z, l4.z); split_tf32(a[3], h4.w, l4.w);
            *(float4*)&AfH[(size_t)tid * 4] = h4;
            *(float4*)&AfL[(size_t)tid * 4] = l4;
            split_tf32(a[4], h4.x, l4.x); split_tf32(a[5], h4.y, l4.y);
            split_tf32(a[6], h4.z, l4.z); split_tf32(a[7], h4.w, l4.w);
            *(float4*)&AfH[(size_t)(tid + 256) * 4] = h4;
            *(float4*)&AfL[(size_t)(tid + 256) * 4] = l4;
            #pragma unroll
            for (int i = 0; i < 4; ++i) {
                float2 h2, l2;
                split_tf32(b[2 * i],     h2.x, l2.x);
                split_tf32(b[2 * i + 1], h2.y, l2.y);
                *(float2*)&BfH[(size_t)(tid + i * 256) * 2] = h2;
                *(float2*)&BfL[(size_t)(tid + i * 256) * 2] = l2;
            }
        }
        __syncthreads();

        // ---- prefetch next tile globals (latency overlaps MMA phase) ----
        if (tile + 1 < NT) {
            const int off = (tile + 1) * 32;
            const float* Xc = X + ck + off;
            const float* Wc = W + ck + off;
            a[0] = Xc[(size_t)(arow     ) * D_SZ];
            a[1] = Xc[(size_t)(arow +  8) * D_SZ];
            a[2] = Xc[(size_t)(arow     ) * D_SZ + 4];
            a[3] = Xc[(size_t)(arow +  8) * D_SZ + 4];
            a[4] = Xc[(size_t)(arow + 32) * D_SZ];
            a[5] = Xc[(size_t)(arow + 40) * D_SZ];
            a[6] = Xc[(size_t)(arow + 32) * D_SZ + 4];
            a[7] = Xc[(size_t)(arow + 40) * D_SZ + 4];
            #pragma unroll
            for (int i = 0; i < 4; ++i) {
                b[2 * i]     = Wc[(size_t)(brow + i * 16) * D_SZ];
                b[2 * i + 1] = Wc[(size_t)(brow + i * 16) * D_SZ + 4];
            }
        }

        // ---- MMA phase: 4 k8-steps x 4 n-subtiles x 3 compensation MMAs ----
        #pragma unroll
        for (int ks = 0; ks < 4; ++ks) {
            const int aidx = ((wm * 4 + ks) * 32 + lane) * 4;
            const float4 ah4 = *(const float4*)&AfH[aidx];
            const float4 al4 = *(const float4*)&AfL[aidx];
            const uint32_t ah0 = __float_as_uint(ah4.x);
            const uint32_t ah1 = __float_as_uint(ah4.y);
            const uint32_t ah2 = __float_as_uint(ah4.z);
            const uint32_t ah3 = __float_as_uint(ah4.w);
            const uint32_t al0 = __float_as_uint(al4.x);
            const uint32_t al1 = __float_as_uint(al4.y);
            const uint32_t al2 = __float_as_uint(al4.z);
            const uint32_t al3 = __float_as_uint(al4.w);

            #pragma unroll
            for (int j = 0; j < 4; ++j) {
                const int bidx = (((wn * 4 + j) * 4 + ks) * 32 + lane) * 2;
                const float2 bh2 = *(const float2*)&BfH[bidx];
                const float2 bl2 = *(const float2*)&BfL[bidx];
                const uint32_t bh0 = __float_as_uint(bh2.x);
                const uint32_t bh1 = __float_as_uint(bh2.y);
                const uint32_t bl0 = __float_as_uint(bl2.x);
                const uint32_t bl1 = __float_as_uint(bl2.y);

                mma_tf32(acc[j][0], acc[j][1], acc[j][2], acc[j][3],
                         ah0, ah1, ah2, ah3, bh0, bh1);
                mma_tf32(acc[j][0], acc[j][1], acc[j][2], acc[j][3],
                         ah0, ah1, ah2, ah3, bl0, bl1);
                mma_tf32(acc[j][0], acc[j][1], acc[j][2], acc[j][3],
                         al0, al1, al2, al3, bh0, bh1);
            }
        }
        __syncthreads();
    }

    // ---- write outputs: d0/d1 -> (row g, cols 2t,2t+1); d2/d3 -> row g+8
    const int row0 = m0 + wm * 16 + g;
    const int row1 = row0 + 8;
    #pragma unroll
    for (int j = 0; j < 4; ++j) {
        const int colb = n0 + wn * 32 + j * 8 + 2 * t;
        float2 v0 = make_float2(acc[j][0], acc[j][1]);
        float2 v1 = make_float2(acc[j][2], acc[j][3]);
        if (act) {
            const float b0 = Wo_b[colb], b1 = Wo_b[colb + 1];
            v0.x = 1.0f / (1.0f + __expf(-(v0.x + b0)));
            v0.y = 1.0f / (1.0f + __expf(-(v0.y + b1)));
            v1.x = 1.0f / (1.0f + __expf(-(v1.x + b0)));
            v1.y = 1.0f / (1.0f + __expf(-(v1.y + b1)));
        }
        *(float2*)(Y + (size_t)row0 * D_SZ + colb) = v0;
        *(float2*)(Y + (size_t)row1 * D_SZ + colb) = v1;
    }
}

// ---------------- gate kernel: i_t, f_t (one warp per batch row) ------------
__global__ __launch_bounds__(256) void gates_kernel(
    const float* __restrict__ X,
    const float* __restrict__ wi_w, const float* __restrict__ wi_b,
    const float* __restrict__ wf_w, const float* __restrict__ wf_b)
{
    const int warp = threadIdx.x >> 5;
    const int lane = threadIdx.x & 31;
    const int b    = blockIdx.x * 8 + warp;

    const float4* x4  = (const float4*)(X + (size_t)b * D_SZ);
    const float4* wi4 = (const float4*)wi_w;
    const float4* wf4 = (const float4*)wf_w;

    float si = 0.f, sf = 0.f;
    #pragma unroll
    for (int r = 0; r < 4; ++r) {
        float4 x  = x4[lane + r * 32];
        float4 wi = wi4[lane + r * 32];
        float4 wf = wf4[lane + r * 32];
        si += x.x * wi.x + x.y * wi.y + x.z * wi.z + x.w * wi.w;
        sf += x.x * wf.x + x.y * wf.y + x.z * wf.z + x.w * wf.w;
    }
    #pragma unroll
    for (int o = 16; o; o >>= 1) {
        si += __shfl_down_sync(0xffffffffu, si, o);
        sf += __shfl_down_sync(0xffffffffu, sf, o);
    }
    if (lane == 0) {
        g_it[b] = fminf(expf(si + wi_b[0]), 50.0f);
        g_ft[b] = 1.0f / (1.0f + expf(-(sf + wf_b[0])));
    }
}

// ---------------- fused cell kernel: C_t + h_tilde partial ------------------
// grid(32, 256): 16 rows per block, 16 threads per row, float4 streaming.
__global__ __launch_bounds__(256) void cell_kernel(
    const float* __restrict__ Cprev, float* __restrict__ Ct)
{
    __shared__ __align__(16) float sk[D_SZ];
    __shared__ __align__(16) float sq[D_SZ];
    __shared__ float sv[16];

    const int b   = blockIdx.y;
    const int rb  = blockIdx.x;       // row block 0..31
    const int tid = threadIdx.x;      // 0..255

    if (tid < 128) {
        ((float4*)sk)[tid] = ((const float4*)(g_k + (size_t)b * D_SZ))[tid];
    } else {
        ((float4*)sq)[tid - 128] = ((const float4*)(g_q + (size_t)b * D_SZ))[tid - 128];
    }
    if (tid < 16) sv[tid] = g_v[(size_t)b * D_SZ + rb * 16 + tid];
    __syncthreads();

    const float f  = g_ft[b];
    const float it = g_it[b];
    const int r      = tid >> 4;       // local row 0..15
    const int lane16 = tid & 15;
    const int row    = rb * 16 + r;
    const float ivi  = it * sv[r];

    const float4* cp = (const float4*)(Cprev + (size_t)b * D_SZ * D_SZ + (size_t)row * D_SZ);
    float4*       ct = (float4*)(Ct   + (size_t)b * D_SZ * D_SZ + (size_t)row * D_SZ);
    const float4* k4 = (const float4*)sk;
    const float4* q4 = (const float4*)sq;

    float ht = 0.f;
    #pragma unroll
    for (int j = 0; j < 8; ++j) {
        const int idx = lane16 + j * 16;
        float4 c  = __ldcs(cp + idx);          // stream: no reuse
        float4 kv = k4[idx];
        float4 qv = q4[idx];
        float4 o;
        o.x = f * c.x + ivi * kv.x;
        o.y = f * c.y + ivi * kv.y;
        o.z = f * c.z + ivi * kv.z;
        o.w = f * c.w + ivi * kv.w;
        __stcs(ct + idx, o);                   // stream: no reuse
        ht += o.x * qv.x + o.y * qv.y + o.z * qv.z + o.w * qv.w;
    }
    #pragma unroll
    for (int off = 8; off; off >>= 1)
        ht += __shfl_down_sync(0xffffffffu, ht, off, 16);
    if (lane16 == 0) g_ht[(size_t)b * D_SZ + row] = ht;
}

// ---------------- epilogue: n_t, nq, h, LayerNorm ---------------------------
__global__ __launch_bounds__(256) void epilogue_kernel(
    const float* __restrict__ n_prev,
    const float* __restrict__ ln_g, const float* __restrict__ ln_b,
    float* __restrict__ out_h, float* __restrict__ out_n)
{
    __shared__ float  red1[8];
    __shared__ float2 red2[8];

    const int b   = blockIdx.x;
    const int tid = threadIdx.x;
    const int e0  = tid;
    const int e1  = tid + 256;
    const size_t base = (size_t)b * D_SZ;

    const float f  = g_ft[b];
    const float it = g_it[b];

    const float np0 = n_prev[base + e0], np1 = n_prev[base + e1];
    const float k0  = g_k[base + e0],   k1  = g_k[base + e1];
    const float q0  = g_q[base + e0],   q1  = g_q[base + e1];
    const float o0  = g_o[base + e0],   o1  = g_o[base + e1];
    const float t0  = g_ht[base + e0],  t1  = g_ht[base + e1];
    const float gg0 = ln_g[e0],         gg1 = ln_g[e1];
    const float bb0 = ln_b[e0],         bb1 = ln_b[e1];

    const float nt0 = f * np0 + it * k0;
    const float nt1 = f * np1 + it * k1;
    out_n[base + e0] = nt0;
    out_n[base + e1] = nt1;

    float nq = nt0 * q0 + nt1 * q1;
    {
        #pragma unroll
        for (int o = 16; o; o >>= 1) nq += __shfl_down_sync(0xffffffffu, nq, o);
        const int w = tid >> 5;
        if ((tid & 31) == 0) red1[w] = nq;
        __syncthreads();
        if (tid < 8) {
            float s = red1[tid];
            #pragma unroll
            for (int o = 4; o; o >>= 1) s += __shfl_down_sync(0xffu, s, o);
            if (tid == 0) red1[0] = s;
        }
        __syncthreads();
        nq = red1[0];
    }
    const float inv_den = 1.0f / fmaxf(fabsf(nq), 1.0f);

    const float h0 = o0 * t0 * inv_den;
    const float h1 = o1 * t1 * inv_den;

    float s  = h0 + h1;
    float s2 = h0 * h0 + h1 * h1;
    {
        #pragma unroll
        for (int o = 16; o; o >>= 1) {
            s  += __shfl_down_sync(0xffffffffu, s,  o);
            s2 += __shfl_down_sync(0xffffffffu, s2, o);
        }
        const int w = tid >> 5;
        if ((tid & 31) == 0) red2[w] = make_float2(s, s2);
        __syncthreads();
        if (tid < 8) {
            float2 v = red2[tid];
            #pragma unroll
            for (int o = 4; o; o >>= 1) {
                v.x += __shfl_down_sync(0xffu, v.x, o);
                v.y += __shfl_down_sync(0xffu, v.y, o);
            }
            if (tid == 0) red2[0] = v;
        }
        __syncthreads();
        s  = red2[0].x;
        s2 = red2[0].y;
    }

    const float mu   = s * (1.0f / (float)D_SZ);
    const float var  = fmaxf(s2 * (1.0f / (float)D_SZ) - mu * mu, 0.0f);
    const float rstd = rsqrtf(var + 1e-5f);

    out_h[base + e0] = (h0 - mu) * rstd * gg0 + bb0;
    out_h[base + e1] = (h1 - mu) * rstd * gg1 + bb1;
}

// ---------------- launch ----------------------------------------------------
extern "C" void kernel_launch(void* const* d_in, const int* in_sizes, int n_in,
                              void* d_out, int out_size)
{
    const float* x_t    = (const float*)d_in[0];
    const float* C_prev = (const float*)d_in[1];
    const float* n_prev = (const float*)d_in[2];
    const float* Wq     = (const float*)d_in[3];
    const float* Wk     = (const float*)d_in[4];
    const float* Wv     = (const float*)d_in[5];
    const float* wi_w   = (const float*)d_in[6];
    const float* wi_b   = (const float*)d_in[7];
    const float* wf_w   = (const float*)d_in[8];
    const float* wf_b   = (const float*)d_in[9];
    const float* Wo     = (const float*)d_in[10];
    const float* Wo_b   = (const float*)d_in[11];
    const float* ln_g   = (const float*)d_in[12];
    const float* ln_b   = (const float*)d_in[13];

    float* out   = (float*)d_out;
    float* out_h = out;                                       // [256,512]
    float* out_C = out + (size_t)B_SZ * D_SZ;                 // [256,512,512]
    float* out_n = out + (size_t)B_SZ * D_SZ + (size_t)B_SZ * D_SZ * D_SZ; // [256,512]

    gates_kernel<<<B_SZ / 8, 256>>>(x_t, wi_w, wi_b, wf_w, wf_b);
    proj_gemm<<<dim3(8, 4, 4), 256>>>(x_t, Wq, Wk, Wv, Wo, Wo_b);
    cell_kernel<<<dim3(D_SZ / 16, B_SZ), 256>>>(C_prev, out_C);
    epilogue_kernel<<<B_SZ, 256>>>(n_prev, ln_g, ln_b, out_h, out_n);
}